// round 11
// baseline (speedup 1.0000x reference)
#include <cuda_runtime.h>
#include <cstdint>

#define BB 2
#define NPTS 8192
#define BLK 128
#define Q 8
#define RPAIR (Q/2)          // 4
#define TILEM (BLK*Q)        // 1024 ref rows per block
#define NTILE (NPTS/TILEM)   // 8
#define SPLITC 256           // pred candidates per block
#define NSPL (NPTS/SPLITC)   // 32
#define NW (BLK/32)          // 4 warps
#define CGRP 32
#define NGRP (SPLITC/CGRP)   // 8
#define FBLKS 128
#define FBLK_T 128

typedef unsigned long long ull;

// Scratch (device globals, zero-initialized; atomicMax with inverted keys means
// 0 == "worst", so zero state is valid init and final_kernel resets to 0).
__device__ ull      g_closest[BB*NPTS];  // per ref m: (~fkey(u_stuffed)<<32) | (~pred_idx)
__device__ unsigned g_minxy[BB*NPTS];    // per pred n: ~fkey(min d2)
__device__ double   g_part[FBLKS*4];
__device__ unsigned g_ctr;

__device__ __forceinline__ ull fma2(ull a, ull b, ull c){
    ull d; asm("fma.rn.f32x2 %0, %1, %2, %3;" : "=l"(d) : "l"(a), "l"(b), "l"(c)); return d;
}
__device__ __forceinline__ ull add2(ull a, ull b){
    ull d; asm("add.rn.f32x2 %0, %1, %2;" : "=l"(d) : "l"(a), "l"(b)); return d;
}
__device__ __forceinline__ ull pk2(float lo, float hi){
    ull v; asm("mov.b64 %0, {%1, %2};" : "=l"(v)
               : "r"(__float_as_uint(lo)), "r"(__float_as_uint(hi)));
    return v;
}
__device__ __forceinline__ void unpk(ull v, float& lo, float& hi){
    unsigned a, b;
    asm("mov.b64 {%0, %1}, %2;" : "=r"(a), "=r"(b) : "l"(v));
    lo = __uint_as_float(a); hi = __uint_as_float(b);
}
// Monotone float->uint key (handles negatives), invertible.
__device__ __forceinline__ unsigned fkey(float f){
    unsigned b = __float_as_uint(f);
    return b ^ ((unsigned)((int)b >> 31) | 0x80000000u);
}
__device__ __forceinline__ float funkey(unsigned u){
    unsigned b = u ^ ((u & 0x80000000u) ? 0x80000000u : 0xFFFFFFFFu);
    return __uint_as_float(b);
}

// Fused single pass, branchless + shuffle-free, f32x2-packed over row pairs.
//   candidate tuple (dup-packed): (-2px,-2py,-2pz,|p|^2);  u = |p|^2 - 2 p.r
//   ref-side argmin key: u low 8 mantissa bits = candidate slot (LOP3) + FMNMX, in-thread
//   pred-side min: d2 = u + |r|^2 (ADD2), FMNMX accums, warp-private smem merge + REDG
__global__ void __launch_bounds__(BLK) dist_kernel(const float* __restrict__ pred_pts,
                                                   const float* __restrict__ ref_pts) {
    __shared__ __align__(16) ull  scand[SPLITC*4];      // per cand: x2,y2,z2,w2 dup-packed
    __shared__ float scol[NW][CGRP][33];                // [warp][cand-in-grp][lane]
    const int b     = blockIdx.z;
    const int tile  = blockIdx.x;
    const int split = blockIdx.y;
    const int tid   = threadIdx.x;
    const int lane  = tid & 31;
    const int wid   = tid >> 5;

    // Stage pred candidates dup-packed
    const int cbase = b*NPTS + split*SPLITC;
    #pragma unroll
    for (int c = tid; c < SPLITC; c += BLK) {
        const float* p = pred_pts + (size_t)(cbase + c) * 3;
        const float x = p[0], y = p[1], z = p[2];
        const float w = x*x + y*y + z*z;
        ull* d = scand + c*4;
        d[0] = pk2(-2.f*x, -2.f*x); d[1] = pk2(-2.f*y, -2.f*y);
        d[2] = pk2(-2.f*z, -2.f*z); d[3] = pk2(w, w);
    }

    // Resident ref rows: slot j in [0,Q); pair k packs (j=k lo, j=k+RPAIR hi)
    const int rbase = b*NPTS + tile*TILEM;
    ull rx2[RPAIR], ry2[RPAIR], rz2[RPAIR], rm2p[RPAIR];
    float aminL[RPAIR], aminH[RPAIR];
    const float INFF = __int_as_float(0x7F800000);
    #pragma unroll
    for (int k = 0; k < RPAIR; k++) {
        const float* rl = ref_pts + (size_t)(rbase + k*BLK + tid) * 3;
        const float* rh = ref_pts + (size_t)(rbase + (k + RPAIR)*BLK + tid) * 3;
        const float ax = rl[0], ay = rl[1], az = rl[2];
        const float bx = rh[0], by = rh[1], bz = rh[2];
        rx2[k] = pk2(ax, bx); ry2[k] = pk2(ay, by); rz2[k] = pk2(az, bz);
        rm2p[k] = pk2(ax*ax + ay*ay + az*az, bx*bx + by*by + bz*bz);
        aminL[k] = INFF; aminH[k] = INFF;
    }
    __syncthreads();

    const ulonglong2* c2 = (const ulonglong2*)scand;

    for (int g = 0; g < NGRP; g++) {
        #pragma unroll 4
        for (int ci = 0; ci < CGRP; ci++) {
            const int c = g*CGRP + ci;
            const ulonglong2 A = c2[c*2];       // x2, y2
            const ulonglong2 Bv = c2[c*2 + 1];  // z2, w2
            float colA = INFF, colB = INFF;
            #pragma unroll
            for (int k = 0; k < RPAIR; k++) {
                const ull u2 = fma2(A.x, rx2[k], fma2(A.y, ry2[k], fma2(Bv.x, rz2[k], Bv.y)));
                const ull dd = add2(u2, rm2p[k]);
                float dlo, dhi; unpk(dd, dlo, dhi);
                colA = fminf(colA, dlo); colB = fminf(colB, dhi);
                float ulo, uhi; unpk(u2, ulo, uhi);
                const float sl = __uint_as_float((__float_as_uint(ulo) & 0xFFFFFF00u) | (unsigned)c);
                const float sh = __uint_as_float((__float_as_uint(uhi) & 0xFFFFFF00u) | (unsigned)c);
                aminL[k] = fminf(aminL[k], sl);
                aminH[k] = fminf(aminH[k], sh);
            }
            scol[wid][ci][lane] = fminf(colA, colB);   // warp-private, no sync
        }
        // lane-parallel column reduce: lane l handles candidate g*CGRP + l
        float v = scol[wid][lane][0];
        #pragma unroll
        for (int k = 1; k < 32; k++) v = fminf(v, scol[wid][lane][k]);
        atomicMax(&g_minxy[cbase + g*CGRP + lane], ~fkey(v));
    }

    // Flush per-row argmin partials
    #pragma unroll
    for (int k = 0; k < RPAIR; k++) {
        const unsigned slL = __float_as_uint(aminL[k]) & 0xFFu;
        const unsigned slH = __float_as_uint(aminH[k]) & 0xFFu;
        const unsigned idxL = (unsigned)(split*SPLITC + (int)slL);
        const unsigned idxH = (unsigned)(split*SPLITC + (int)slH);
        atomicMax(&g_closest[rbase + k*BLK + tid],
                  ((ull)(~fkey(aminL[k])) << 32) | (ull)(unsigned)(~idxL));
        atomicMax(&g_closest[rbase + (k + RPAIR)*BLK + tid],
                  ((ull)(~fkey(aminH[k])) << 32) | (ull)(unsigned)(~idxH));
    }
}

// Finalization: exact d_yx recompute at the winning index, warp-shuffle reduce,
// last-block combine (deterministic fixed-order trees). Resets state for replay.
__global__ void __launch_bounds__(FBLK_T) final_kernel(const float* __restrict__ pred_pts,
                                                       const float* __restrict__ ref_pts,
                                                       const float* __restrict__ pred_sdfs,
                                                       const float* __restrict__ pred_cols,
                                                       const float* __restrict__ ref_sdfs,
                                                       const float* __restrict__ ref_cols,
                                                       float* __restrict__ out) {
    const int i = blockIdx.x * FBLK_T + threadIdx.x;   // [0, BB*NPTS)
    const int b = i >> 13;
    const int lane = threadIdx.x & 31;
    const int wid = threadIdx.x >> 5;

    const ull P = g_closest[i];
    const unsigned idx = ~(unsigned)P;                 // winning pred index for ref row i

    // Exact squared distance ref_i -> pred_idx (difference form)
    const float* rp = ref_pts + (size_t)i * 3;
    const float* pp = pred_pts + ((size_t)(b << 13) + idx) * 3;
    const float dx = rp[0]-pp[0], dy = rp[1]-pp[1], dz = rp[2]-pp[2];
    const float d_yx = fmaf(dz, dz, fmaf(dy, dy, dx*dx));

    const float d_xy = fmaxf(funkey(~g_minxy[i]), 0.f);   // pred row i min d2

    // Reset state for next graph replay (each i touched by exactly one thread)
    g_closest[i] = 0ull;
    g_minxy[i]   = 0u;

    const float* pc = pred_cols + (size_t)i * 3;
    const float* rc = ref_cols + ((size_t)(b << 13) + idx) * 3;
    double vals[4];
    vals[0] = fabsf(ref_sdfs[(b << 13) + idx] - pred_sdfs[i]);
    vals[1] = (double)(fabsf(rc[0]-pc[0]) + fabsf(rc[1]-pc[1]) + fabsf(rc[2]-pc[2]));
    vals[2] = d_yx;
    vals[3] = d_xy;

    __shared__ double sred[4][4];   // [warp][k]
    #pragma unroll
    for (int k = 0; k < 4; k++) {
        double v = vals[k];
        #pragma unroll
        for (int s = 16; s > 0; s >>= 1) v += __shfl_down_sync(0xFFFFFFFFu, v, s);
        if (lane == 0) sred[wid][k] = v;
    }
    __syncthreads();
    if (threadIdx.x == 0) {
        #pragma unroll
        for (int k = 0; k < 4; k++)
            g_part[blockIdx.x * 4 + k] = sred[0][k] + sred[1][k] + sred[2][k] + sred[3][k];
    }

    __threadfence();
    __shared__ unsigned ticket;
    if (threadIdx.x == 0) ticket = atomicAdd(&g_ctr, 1u);
    __syncthreads();
    if (ticket != FBLKS - 1) return;

    __threadfence();
    volatile double* vp = (volatile double*)g_part;
    double tv[4];
    #pragma unroll
    for (int k = 0; k < 4; k++) tv[k] = vp[threadIdx.x * 4 + k];  // thread t = block t's partial
    #pragma unroll
    for (int k = 0; k < 4; k++) {
        double v = tv[k];
        #pragma unroll
        for (int s = 16; s > 0; s >>= 1) v += __shfl_down_sync(0xFFFFFFFFu, v, s);
        if (lane == 0) sred[wid][k] = v;
    }
    __syncthreads();
    if (threadIdx.x == 0) {
        const double t0 = sred[0][0] + sred[1][0] + sred[2][0] + sred[3][0];
        const double t1 = sred[0][1] + sred[1][1] + sred[2][1] + sred[3][1];
        const double t2 = sred[0][2] + sred[1][2] + sred[2][2] + sred[3][2];
        const double t3 = sred[0][3] + sred[1][3] + sred[2][3] + sred[3][3];
        out[0] = (float)(t0 / (double)(BB * NPTS));
        out[1] = (float)(t1 / (double)(BB * NPTS * 3));
        out[2] = (float)(t3 / (double)(BB * NPTS) + t2 / (double)(BB * NPTS));
        g_ctr = 0;   // reset ticket counter for next replay
    }
}

extern "C" void kernel_launch(void* const* d_in, const int* in_sizes, int n_in,
                              void* d_out, int out_size) {
    const float* pred_pts  = (const float*)d_in[0];
    const float* pred_sdfs = (const float*)d_in[1];
    const float* pred_cols = (const float*)d_in[2];
    const float* ref_pts   = (const float*)d_in[3];
    const float* ref_sdfs  = (const float*)d_in[4];
    const float* ref_cols  = (const float*)d_in[5];
    float* out = (float*)d_out;

    dist_kernel<<<dim3(NTILE, NSPL, BB), BLK>>>(pred_pts, ref_pts);
    final_kernel<<<FBLKS, FBLK_T>>>(pred_pts, ref_pts, pred_sdfs, pred_cols,
                                    ref_sdfs, ref_cols, out);
}

// round 12
// speedup vs baseline: 1.1127x; 1.1127x over previous
#include <cuda_runtime.h>
#include <cstdint>

#define BB 2
#define NPTS 8192
#define BLK 128
#define Q 8
#define RPAIR (Q/2)          // 4
#define TILEM (BLK*Q)        // 1024 ref rows per block
#define NTILE (NPTS/TILEM)   // 8
#define SPLITC 128           // pred candidates per block
#define NSPL (NPTS/SPLITC)   // 64
#define NW (BLK/32)          // 4 warps
#define CGRP 32
#define NGRP (SPLITC/CGRP)   // 4
#define FBLKS 128
#define FBLK_T 128

typedef unsigned long long ull;

// Scratch (device globals, zero-initialized; atomicMax with inverted keys means
// 0 == "worst", so zero state is valid init and final_kernel resets to 0).
__device__ ull      g_closest[BB*NPTS];  // per ref m: (~fkey(u_stuffed)<<32) | (~pred_idx)
__device__ unsigned g_minxy[BB*NPTS];    // per pred n: ~fkey(min d2)
__device__ double   g_part[FBLKS*4];
__device__ unsigned g_ctr;

__device__ __forceinline__ ull fma2(ull a, ull b, ull c){
    ull d; asm("fma.rn.f32x2 %0, %1, %2, %3;" : "=l"(d) : "l"(a), "l"(b), "l"(c)); return d;
}
__device__ __forceinline__ ull add2(ull a, ull b){
    ull d; asm("add.rn.f32x2 %0, %1, %2;" : "=l"(d) : "l"(a), "l"(b)); return d;
}
__device__ __forceinline__ ull pk2(float lo, float hi){
    ull v; asm("mov.b64 %0, {%1, %2};" : "=l"(v)
               : "r"(__float_as_uint(lo)), "r"(__float_as_uint(hi)));
    return v;
}
__device__ __forceinline__ void unpk(ull v, float& lo, float& hi){
    unsigned a, b;
    asm("mov.b64 {%0, %1}, %2;" : "=r"(a), "=r"(b) : "l"(v));
    lo = __uint_as_float(a); hi = __uint_as_float(b);
}
// Monotone float->uint key (handles negatives), invertible.
__device__ __forceinline__ unsigned fkey(float f){
    unsigned b = __float_as_uint(f);
    return b ^ ((unsigned)((int)b >> 31) | 0x80000000u);
}
__device__ __forceinline__ float funkey(unsigned u){
    unsigned b = u ^ ((u & 0x80000000u) ? 0x80000000u : 0xFFFFFFFFu);
    return __uint_as_float(b);
}

// Fused single pass, branchless + shuffle-free, f32x2-packed over row pairs.
//   candidate tuple (dup-packed): (-2px,-2py,-2pz,|p|^2);  u = |p|^2 - 2 p.r
//   ref-side argmin key: u low 8 mantissa bits = candidate slot (LOP3) + FMNMX, in-thread
//   pred-side min: d2 = u + |r|^2 (ADD2), FMNMX accums, warp-private smem merge + REDG
__global__ void __launch_bounds__(BLK) dist_kernel(const float* __restrict__ pred_pts,
                                                   const float* __restrict__ ref_pts) {
    __shared__ __align__(16) ull  scand[SPLITC*4];      // per cand: x2,y2,z2,w2 dup-packed
    __shared__ float scol[NW][CGRP][33];                // [warp][cand-in-grp][lane]
    const int b     = blockIdx.z;
    const int tile  = blockIdx.x;
    const int split = blockIdx.y;
    const int tid   = threadIdx.x;
    const int lane  = tid & 31;
    const int wid   = tid >> 5;

    // Stage pred candidates dup-packed
    const int cbase = b*NPTS + split*SPLITC;
    #pragma unroll
    for (int c = tid; c < SPLITC; c += BLK) {
        const float* p = pred_pts + (size_t)(cbase + c) * 3;
        const float x = p[0], y = p[1], z = p[2];
        const float w = x*x + y*y + z*z;
        ull* d = scand + c*4;
        d[0] = pk2(-2.f*x, -2.f*x); d[1] = pk2(-2.f*y, -2.f*y);
        d[2] = pk2(-2.f*z, -2.f*z); d[3] = pk2(w, w);
    }

    // Resident ref rows: slot j in [0,Q); pair k packs (j=k lo, j=k+RPAIR hi)
    const int rbase = b*NPTS + tile*TILEM;
    ull rx2[RPAIR], ry2[RPAIR], rz2[RPAIR], rm2p[RPAIR];
    float aminL[RPAIR], aminH[RPAIR];
    const float INFF = __int_as_float(0x7F800000);
    #pragma unroll
    for (int k = 0; k < RPAIR; k++) {
        const float* rl = ref_pts + (size_t)(rbase + k*BLK + tid) * 3;
        const float* rh = ref_pts + (size_t)(rbase + (k + RPAIR)*BLK + tid) * 3;
        const float ax = rl[0], ay = rl[1], az = rl[2];
        const float bx = rh[0], by = rh[1], bz = rh[2];
        rx2[k] = pk2(ax, bx); ry2[k] = pk2(ay, by); rz2[k] = pk2(az, bz);
        rm2p[k] = pk2(ax*ax + ay*ay + az*az, bx*bx + by*by + bz*bz);
        aminL[k] = INFF; aminH[k] = INFF;
    }
    __syncthreads();

    const ulonglong2* c2 = (const ulonglong2*)scand;

    for (int g = 0; g < NGRP; g++) {
        #pragma unroll 4
        for (int ci = 0; ci < CGRP; ci++) {
            const int c = g*CGRP + ci;
            const ulonglong2 A = c2[c*2];       // x2, y2
            const ulonglong2 Bv = c2[c*2 + 1];  // z2, w2
            float colA = INFF, colB = INFF;
            #pragma unroll
            for (int k = 0; k < RPAIR; k++) {
                const ull u2 = fma2(A.x, rx2[k], fma2(A.y, ry2[k], fma2(Bv.x, rz2[k], Bv.y)));
                const ull dd = add2(u2, rm2p[k]);
                float dlo, dhi; unpk(dd, dlo, dhi);
                colA = fminf(colA, dlo); colB = fminf(colB, dhi);
                float ulo, uhi; unpk(u2, ulo, uhi);
                const float sl = __uint_as_float((__float_as_uint(ulo) & 0xFFFFFF00u) | (unsigned)c);
                const float sh = __uint_as_float((__float_as_uint(uhi) & 0xFFFFFF00u) | (unsigned)c);
                aminL[k] = fminf(aminL[k], sl);
                aminH[k] = fminf(aminH[k], sh);
            }
            scol[wid][ci][lane] = fminf(colA, colB);   // warp-private, no sync
        }
        // lane-parallel column reduce: lane l handles candidate g*CGRP + l
        float v = scol[wid][lane][0];
        #pragma unroll
        for (int k = 1; k < 32; k++) v = fminf(v, scol[wid][lane][k]);
        atomicMax(&g_minxy[cbase + g*CGRP + lane], ~fkey(v));
    }

    // Flush per-row argmin partials
    #pragma unroll
    for (int k = 0; k < RPAIR; k++) {
        const unsigned slL = __float_as_uint(aminL[k]) & 0xFFu;
        const unsigned slH = __float_as_uint(aminH[k]) & 0xFFu;
        const unsigned idxL = (unsigned)(split*SPLITC + (int)slL);
        const unsigned idxH = (unsigned)(split*SPLITC + (int)slH);
        atomicMax(&g_closest[rbase + k*BLK + tid],
                  ((ull)(~fkey(aminL[k])) << 32) | (ull)(unsigned)(~idxL));
        atomicMax(&g_closest[rbase + (k + RPAIR)*BLK + tid],
                  ((ull)(~fkey(aminH[k])) << 32) | (ull)(unsigned)(~idxH));
    }
}

// Finalization: exact d_yx recompute at the winning index, warp-shuffle reduce,
// last-block combine (deterministic fixed-order trees). Resets state for replay.
__global__ void __launch_bounds__(FBLK_T) final_kernel(const float* __restrict__ pred_pts,
                                                       const float* __restrict__ ref_pts,
                                                       const float* __restrict__ pred_sdfs,
                                                       const float* __restrict__ pred_cols,
                                                       const float* __restrict__ ref_sdfs,
                                                       const float* __restrict__ ref_cols,
                                                       float* __restrict__ out) {
    const int i = blockIdx.x * FBLK_T + threadIdx.x;   // [0, BB*NPTS)
    const int b = i >> 13;
    const int lane = threadIdx.x & 31;
    const int wid = threadIdx.x >> 5;

    const ull P = g_closest[i];
    const unsigned idx = ~(unsigned)P;                 // winning pred index for ref row i

    // Exact squared distance ref_i -> pred_idx (difference form)
    const float* rp = ref_pts + (size_t)i * 3;
    const float* pp = pred_pts + ((size_t)(b << 13) + idx) * 3;
    const float dx = rp[0]-pp[0], dy = rp[1]-pp[1], dz = rp[2]-pp[2];
    const float d_yx = fmaf(dz, dz, fmaf(dy, dy, dx*dx));

    const float d_xy = fmaxf(funkey(~g_minxy[i]), 0.f);   // pred row i min d2

    // Reset state for next graph replay (each i touched by exactly one thread)
    g_closest[i] = 0ull;
    g_minxy[i]   = 0u;

    const float* pc = pred_cols + (size_t)i * 3;
    const float* rc = ref_cols + ((size_t)(b << 13) + idx) * 3;
    double vals[4];
    vals[0] = fabsf(ref_sdfs[(b << 13) + idx] - pred_sdfs[i]);
    vals[1] = (double)(fabsf(rc[0]-pc[0]) + fabsf(rc[1]-pc[1]) + fabsf(rc[2]-pc[2]));
    vals[2] = d_yx;
    vals[3] = d_xy;

    __shared__ double sred[4][4];   // [warp][k]
    #pragma unroll
    for (int k = 0; k < 4; k++) {
        double v = vals[k];
        #pragma unroll
        for (int s = 16; s > 0; s >>= 1) v += __shfl_down_sync(0xFFFFFFFFu, v, s);
        if (lane == 0) sred[wid][k] = v;
    }
    __syncthreads();
    if (threadIdx.x == 0) {
        #pragma unroll
        for (int k = 0; k < 4; k++)
            g_part[blockIdx.x * 4 + k] = sred[0][k] + sred[1][k] + sred[2][k] + sred[3][k];
    }

    __threadfence();
    __shared__ unsigned ticket;
    if (threadIdx.x == 0) ticket = atomicAdd(&g_ctr, 1u);
    __syncthreads();
    if (ticket != FBLKS - 1) return;

    __threadfence();
    volatile double* vp = (volatile double*)g_part;
    double tv[4];
    #pragma unroll
    for (int k = 0; k < 4; k++) tv[k] = vp[threadIdx.x * 4 + k];  // thread t = block t's partial
    #pragma unroll
    for (int k = 0; k < 4; k++) {
        double v = tv[k];
        #pragma unroll
        for (int s = 16; s > 0; s >>= 1) v += __shfl_down_sync(0xFFFFFFFFu, v, s);
        if (lane == 0) sred[wid][k] = v;
    }
    __syncthreads();
    if (threadIdx.x == 0) {
        const double t0 = sred[0][0] + sred[1][0] + sred[2][0] + sred[3][0];
        const double t1 = sred[0][1] + sred[1][1] + sred[2][1] + sred[3][1];
        const double t2 = sred[0][2] + sred[1][2] + sred[2][2] + sred[3][2];
        const double t3 = sred[0][3] + sred[1][3] + sred[2][3] + sred[3][3];
        out[0] = (float)(t0 / (double)(BB * NPTS));
        out[1] = (float)(t1 / (double)(BB * NPTS * 3));
        out[2] = (float)(t3 / (double)(BB * NPTS) + t2 / (double)(BB * NPTS));
        g_ctr = 0;   // reset ticket counter for next replay
    }
}

extern "C" void kernel_launch(void* const* d_in, const int* in_sizes, int n_in,
                              void* d_out, int out_size) {
    const float* pred_pts  = (const float*)d_in[0];
    const float* pred_sdfs = (const float*)d_in[1];
    const float* pred_cols = (const float*)d_in[2];
    const float* ref_pts   = (const float*)d_in[3];
    const float* ref_sdfs  = (const float*)d_in[4];
    const float* ref_cols  = (const float*)d_in[5];
    float* out = (float*)d_out;

    dist_kernel<<<dim3(NTILE, NSPL, BB), BLK>>>(pred_pts, ref_pts);
    final_kernel<<<FBLKS, FBLK_T>>>(pred_pts, ref_pts, pred_sdfs, pred_cols,
                                    ref_sdfs, ref_cols, out);
}